// round 1
// baseline (speedup 1.0000x reference)
#include <cuda_runtime.h>
#include <cstdint>

// Problem constants
#define HOP     128
#define WINL    512
#define PADW    192
#define NB      32
#define NT      131072
#define NFRM    1024          // frames per batch row
#define NSTAGE  11

// Tiling
#define NFB     64                         // frames per block (== threads per block)
#define BLK_PER_B (NFRM / NFB)             // 16
#define SPAN    ((NFB - 1) * HOP + WINL)   // 8576 samples covered by a block
#define NROWS   (SPAN / HOP)               // 67
#define SMEMN   (NROWS * (HOP + 1))        // 8643 floats (129-word padded rows)
#define SMEM_BYTES ((2 * SMEMN + WINL) * sizeof(float))   // 71192 B

#define TWO_PI_OVER_WIN 0.012271846303085129f   // 2*pi/512

__device__ __forceinline__ int pidx(int i) { return i + (i >> 7); }  // bank-conflict-free stride-128 access

__device__ __forceinline__ float hannw(int n) {
    return 0.5f - 0.5f * __cosf((float)n * TWO_PI_OVER_WIN);
}

// OLA normalization at padded position p (sum of hann over covering frames).
__device__ float norm_at(int p) {
    int f_hi = p >> 7; if (f_hi > NFRM - 1) f_hi = NFRM - 1;
    int f_lo = (p >= 384) ? ((p - 384) >> 7) : 0;
    float s = 0.f;
    for (int f = f_lo; f <= f_hi; ++f) s += hannw(p - (f << 7));
    return s;
}

// Zero the 384-wide inter-block halo columns of d_out that receive atomicAdds.
__global__ void halo_zero_kernel(float* __restrict__ out) {
    int b   = blockIdx.y;
    int blk = blockIdx.x + 1;                 // 1..BLK_PER_B-1
    int u   = blk * (NFB * HOP) - PADW + (int)threadIdx.x;   // 384 threads
    out[(size_t)b * NT + u] = 0.f;
}

__global__ __launch_bounds__(NFB) void synth_kernel(const float* __restrict__ ex,
                                                    const float* __restrict__ gain,
                                                    const float* __restrict__ bq,
                                                    float* __restrict__ out) {
    extern __shared__ float sm[];
    float* in_s  = sm;                // SMEMN floats
    float* out_s = sm + SMEMN;        // SMEMN floats
    float* win_s = sm + 2 * SMEMN;    // WINL floats

    const int b   = blockIdx.y;
    const int blk = blockIdx.x;
    const int F0  = blk * NFB;
    const int S0  = F0 * HOP;         // padded-position offset of this block
    const int tid = (int)threadIdx.x;

    // ---- Phase A: coalesced load of the input span (with zero padding), zero OLA buffer, window table
    for (int i = tid; i < SPAN; i += NFB) {
        int pos = S0 + i - PADW;
        float v = (pos >= 0 && pos < NT) ? ex[(size_t)b * NT + pos] : 0.f;
        in_s[pidx(i)] = v;
    }
    for (int i = tid; i < SMEMN; i += NFB) out_s[i] = 0.f;
    for (int i = tid; i < WINL; i += NFB)  win_s[i] = hannw(i);
    __syncthreads();

    // ---- Per-frame setup
    const int f = F0 + tid;
    const float g = gain[b * NFRM + f];
    float a1[NSTAGE], a2[NSTAGE];
    const float* bp = bq + (size_t)(b * NFRM + f) * NSTAGE * 3;
    #pragma unroll
    for (int s = 0; s < NSTAGE; ++s) { a1[s] = bp[s * 3 + 1]; a2[s] = bp[s * 3 + 2]; }

    float pa[NSTAGE], pb[NSTAGE];
    #pragma unroll
    for (int s = 0; s < NSTAGE; ++s) { pa[s] = 0.f; pb[s] = 0.f; }

    const int kbase = tid * (HOP + 1);   // padded smem base for this frame

    // ---- Phase B: software-pipelined cascade.
    // At step t, stage s emits sample (t-s). All 11 stage updates per step are
    // mutually independent (read only previous-step state) -> ILP ~= 22 FMAs/step.
    // Ping-pong roles of pa/pb each step (unrolled x2) to avoid register shuffles.
    // __syncthreads() every 128 output samples makes the in-smem OLA race-free:
    // writers of a given smem address are exactly 128 steps apart.
    for (int t2 = 0; t2 < WINL + NSTAGE - 1; t2 += 2) {
        {   // even step: newest state in pa, write into pb
            const int t = t2;
            float x = (t < WINL) ? in_s[kbase + t + (t >> 7)] * g : 0.f;
            #pragma unroll
            for (int s = 0; s < NSTAGE; ++s) {
                float in = (s == 0) ? x : pa[s - 1];
                pb[s] = fmaf(-a2[s], pb[s], fmaf(-a1[s], pa[s], in));
            }
            if (t >= NSTAGE - 1) {
                int to = t - (NSTAGE - 1);
                int op = kbase + to + (to >> 7);
                out_s[op] = fmaf(pb[NSTAGE - 1], win_s[to], out_s[op]);
            }
        }
        {   // odd step: newest state in pb, write into pa
            const int t = t2 + 1;
            float x = (t < WINL) ? in_s[kbase + t + (t >> 7)] * g : 0.f;
            #pragma unroll
            for (int s = 0; s < NSTAGE; ++s) {
                float in = (s == 0) ? x : pb[s - 1];
                pa[s] = fmaf(-a2[s], pa[s], fmaf(-a1[s], pb[s], in));
            }
            if (t >= NSTAGE - 1) {
                int to = t - (NSTAGE - 1);
                int op = kbase + to + (to >> 7);
                out_s[op] = fmaf(pa[NSTAGE - 1], win_s[to], out_s[op]);
            }
            // barrier at t = 137, 265, 393, 521 (output-window boundaries)
            if (t >= 137 && ((t - 137) & 127) == 0) __syncthreads();
        }
    }
    __syncthreads();  // safety (last in-loop barrier already covers this)

    // ---- Phase C: write out. Interior (all contributing frames in-block) is a
    // plain store; 384-wide halos at block boundaries accumulate via atomicAdd
    // into pre-zeroed columns. Normalization folded in (interior norm == 2).
    const int lo = (F0 == 0) ? 0 : 384;
    const int hi = (F0 + NFB >= NFRM) ? SPAN : NFB * HOP;
    for (int i = tid; i < SPAN; i += NFB) {
        int p = S0 + i;
        int u = p - PADW;
        if (u < 0 || u >= NT) continue;
        float nrm = (p >= 384 && p < NFRM * HOP) ? 2.0f : norm_at(p);
        float w = out_s[pidx(i)] / nrm;
        float* dst = out + (size_t)b * NT + u;
        if (i >= lo && i < hi) *dst = w;
        else                   atomicAdd(dst, w);
    }
}

extern "C" void kernel_launch(void* const* d_in, const int* in_sizes, int n_in,
                              void* d_out, int out_size) {
    const float* ex   = (const float*)d_in[0];   // (32, 131072) f32
    const float* gain = (const float*)d_in[1];   // (32, 1024)   f32
    const float* bq   = (const float*)d_in[2];   // (32, 1024, 11, 3) f32
    float* out = (float*)d_out;                  // (32, 131072) f32

    cudaFuncSetAttribute(synth_kernel, cudaFuncAttributeMaxDynamicSharedMemorySize,
                         (int)SMEM_BYTES);

    halo_zero_kernel<<<dim3(BLK_PER_B - 1, NB), 384>>>(out);
    synth_kernel<<<dim3(BLK_PER_B, NB), NFB, SMEM_BYTES>>>(ex, gain, bq, out);
}

// round 2
// speedup vs baseline: 2.0867x; 2.0867x over previous
#include <cuda_runtime.h>
#include <cstdint>

// Problem constants
#define HOP     128
#define WINL    512
#define PADW    192
#define NB      32
#define NT      131072
#define NFRM    1024
#define NSTAGE  11

// Tiling
#define NFB     64
#define BLK_PER_B (NFRM / NFB)             // 16
#define SPAN    ((NFB - 1) * HOP + WINL)   // 8576
#define NROWS   (SPAN / HOP)               // 67
#define SMEMN   (NROWS * (HOP + 1))        // 8643 floats, 129-padded rows
#define SMEM_BYTES ((2 * SMEMN + WINL) * sizeof(float))

#define TWO_PI_OVER_WIN 0.012271846303085129f

__device__ __forceinline__ int pidx(int i) { return i + (i >> 7); }

__device__ __forceinline__ float hannw(int n) {
    return 0.5f - 0.5f * __cosf((float)n * TWO_PI_OVER_WIN);
}

__device__ float norm_at(int p) {
    int f_hi = p >> 7; if (f_hi > NFRM - 1) f_hi = NFRM - 1;
    int f_lo = (p >= 384) ? ((p - 384) >> 7) : 0;
    float s = 0.f;
    for (int f = f_lo; f <= f_hi; ++f) s += hannw(p - (f << 7));
    return s;
}

__global__ void halo_zero_kernel(float* __restrict__ out) {
    int b   = blockIdx.y;
    int blk = blockIdx.x + 1;
    int u   = blk * (NFB * HOP) - PADW + (int)threadIdx.x;
    out[(size_t)b * NT + u] = 0.f;
}

// One cascade step: DST[s] = -a1[s]*SRC[s] - a2[s]*DST[s] + in(s)
// where in(0)=X, in(s)=SRC[s-1] (previous-step output of prior stage).
// All 11 updates read only previous-step state -> 22 independent FMAs.
#define CASCADE(SRC, DST, X)                                          \
    DST##0  = fmaf(na2_0,  DST##0,  fmaf(na1_0,  SRC##0,  (X)));      \
    DST##1  = fmaf(na2_1,  DST##1,  fmaf(na1_1,  SRC##1,  SRC##0));   \
    DST##2  = fmaf(na2_2,  DST##2,  fmaf(na1_2,  SRC##2,  SRC##1));   \
    DST##3  = fmaf(na2_3,  DST##3,  fmaf(na1_3,  SRC##3,  SRC##2));   \
    DST##4  = fmaf(na2_4,  DST##4,  fmaf(na1_4,  SRC##4,  SRC##3));   \
    DST##5  = fmaf(na2_5,  DST##5,  fmaf(na1_5,  SRC##5,  SRC##4));   \
    DST##6  = fmaf(na2_6,  DST##6,  fmaf(na1_6,  SRC##6,  SRC##5));   \
    DST##7  = fmaf(na2_7,  DST##7,  fmaf(na1_7,  SRC##7,  SRC##6));   \
    DST##8  = fmaf(na2_8,  DST##8,  fmaf(na1_8,  SRC##8,  SRC##7));   \
    DST##9  = fmaf(na2_9,  DST##9,  fmaf(na1_9,  SRC##9,  SRC##8));   \
    DST##10 = fmaf(na2_10, DST##10, fmaf(na1_10, SRC##10, SRC##9));

#define OUTACC(DST, T) {                                              \
    int _to = (T) - (NSTAGE - 1);                                     \
    int _op = kbase + _to + (_to >> 7);                               \
    out_s[_op] = fmaf(DST##10, win_s[_to], out_s[_op]); }

// Pair of steps with input + output (main body). x loads hoisted to top.
#define PAIR_IO(T) {                                                  \
    float _x0 = in_s[kbase + (T)     + (((T)    ) >> 7)] * g;         \
    float _x1 = in_s[kbase + (T) + 1 + (((T) + 1) >> 7)] * g;         \
    CASCADE(pa, pb, _x0); OUTACC(pb, (T));                            \
    CASCADE(pb, pa, _x1); OUTACC(pa, (T) + 1); }

// Prologue pair: input, no output yet.
#define PAIR_IN(T) {                                                  \
    float _x0 = in_s[kbase + (T)     + (((T)    ) >> 7)] * g;         \
    float _x1 = in_s[kbase + (T) + 1 + (((T) + 1) >> 7)] * g;         \
    CASCADE(pa, pb, _x0);                                             \
    CASCADE(pb, pa, _x1); }

// Epilogue pair: zero input, output only.
#define PAIR_OUT(T) {                                                 \
    CASCADE(pa, pb, 0.0f); OUTACC(pb, (T));                           \
    CASCADE(pb, pa, 0.0f); OUTACC(pa, (T) + 1); }

__global__ __launch_bounds__(NFB, 1) void synth_kernel(const float* __restrict__ ex,
                                                       const float* __restrict__ gain,
                                                       const float* __restrict__ bq,
                                                       float* __restrict__ out) {
    extern __shared__ float sm[];
    float* in_s  = sm;
    float* out_s = sm + SMEMN;
    float* win_s = sm + 2 * SMEMN;

    const int b   = blockIdx.y;
    const int blk = blockIdx.x;
    const int F0  = blk * NFB;
    const int S0  = F0 * HOP;
    const int tid = (int)threadIdx.x;

    // ---- Phase A: stage input span, zero OLA buffer, window table
    for (int i = tid; i < SPAN; i += NFB) {
        int pos = S0 + i - PADW;
        float v = (pos >= 0 && pos < NT) ? ex[(size_t)b * NT + pos] : 0.f;
        in_s[pidx(i)] = v;
    }
    for (int i = tid; i < SMEMN; i += NFB) out_s[i] = 0.f;
    for (int i = tid; i < WINL; i += NFB)  win_s[i] = hannw(i);
    __syncthreads();

    // ---- Per-frame coefficients as named registers (negated for FMA form)
    const int f = F0 + tid;
    const float g = gain[b * NFRM + f];
    const float* bp = bq + (size_t)(b * NFRM + f) * (NSTAGE * 3);
    const float na1_0  = -bp[1],  na2_0  = -bp[2];
    const float na1_1  = -bp[4],  na2_1  = -bp[5];
    const float na1_2  = -bp[7],  na2_2  = -bp[8];
    const float na1_3  = -bp[10], na2_3  = -bp[11];
    const float na1_4  = -bp[13], na2_4  = -bp[14];
    const float na1_5  = -bp[16], na2_5  = -bp[17];
    const float na1_6  = -bp[19], na2_6  = -bp[20];
    const float na1_7  = -bp[22], na2_7  = -bp[23];
    const float na1_8  = -bp[25], na2_8  = -bp[26];
    const float na1_9  = -bp[28], na2_9  = -bp[29];
    const float na1_10 = -bp[31], na2_10 = -bp[32];

    float pa0 = 0.f, pa1 = 0.f, pa2 = 0.f, pa3 = 0.f, pa4 = 0.f, pa5 = 0.f,
          pa6 = 0.f, pa7 = 0.f, pa8 = 0.f, pa9 = 0.f, pa10 = 0.f;
    float pb0 = 0.f, pb1 = 0.f, pb2 = 0.f, pb3 = 0.f, pb4 = 0.f, pb5 = 0.f,
          pb6 = 0.f, pb7 = 0.f, pb8 = 0.f, pb9 = 0.f, pb10 = 0.f;

    const int kbase = tid * (HOP + 1);

    // ---- Phase B: software-pipelined cascade (pipeline depth 11; at step t,
    // stage s holds sample t-s). Barriers sit exactly at output-window
    // boundaries (to = 128*w) so cross-warp OLA writers (128 steps apart)
    // are always separated by a barrier.

    // Prologue: t = 0..9, fills the pipeline, no output.
    #pragma unroll
    for (int t = 0; t < NSTAGE - 1; t += 2) PAIR_IN(t);

    // Three uniform chunks: t in [10,138), [138,266), [266,394)
    for (int c = 0; c < 3; ++c) {
        const int t0 = 10 + 128 * c;
        #pragma unroll 2
        for (int t = t0; t < t0 + 128; t += 2) PAIR_IO(t);
        __syncthreads();
    }

    // Chunk 4: t in [394,512) with input...
    #pragma unroll 2
    for (int t = 394; t < 512; t += 2) PAIR_IO(t);
    // ...then drain the pipeline: t in [512,522), zero input.
    #pragma unroll
    for (int t = 512; t < 522; t += 2) PAIR_OUT(t);
    __syncthreads();

    // ---- Phase C: write out. Interior norm is exactly 2.0; halos via atomics
    // into pre-zeroed columns.
    const int lo = (F0 == 0) ? 0 : 384;
    const int hi = (F0 + NFB >= NFRM) ? SPAN : NFB * HOP;
    for (int i = tid; i < SPAN; i += NFB) {
        int p = S0 + i;
        int u = p - PADW;
        if (u < 0 || u >= NT) continue;
        float w = out_s[pidx(i)];
        if (p >= 384 && p < NFRM * HOP) w *= 0.5f;
        else                            w /= norm_at(p);
        float* dst = out + (size_t)b * NT + u;
        if (i >= lo && i < hi) *dst = w;
        else                   atomicAdd(dst, w);
    }
}

extern "C" void kernel_launch(void* const* d_in, const int* in_sizes, int n_in,
                              void* d_out, int out_size) {
    const float* ex   = (const float*)d_in[0];   // (32, 131072) f32
    const float* gain = (const float*)d_in[1];   // (32, 1024)   f32
    const float* bq   = (const float*)d_in[2];   // (32, 1024, 11, 3) f32
    float* out = (float*)d_out;                  // (32, 131072) f32

    cudaFuncSetAttribute(synth_kernel, cudaFuncAttributeMaxDynamicSharedMemorySize,
                         (int)SMEM_BYTES);

    halo_zero_kernel<<<dim3(BLK_PER_B - 1, NB), 384>>>(out);
    synth_kernel<<<dim3(BLK_PER_B, NB), NFB, SMEM_BYTES>>>(ex, gain, bq, out);
}

// round 3
// speedup vs baseline: 2.1979x; 1.0533x over previous
#include <cuda_runtime.h>
#include <cstdint>

// Problem constants
#define HOP     128
#define WINL    512
#define PADW    192
#define NB      32
#define NT      131072
#define NFRM    1024
#define NSTAGE  11

// Tiling
#define NFB     64
#define BLK_PER_B (NFRM / NFB)             // 16
#define SPAN    ((NFB - 1) * HOP + WINL)   // 8576
#define NROWS   (SPAN / HOP)               // 67
#define SMEMN   (NROWS * (HOP + 1))        // 8643 floats, 129-padded rows
#define SMEM_BYTES ((2 * SMEMN + WINL) * sizeof(float))

#define TWO_PI_OVER_WIN 0.012271846303085129f

__device__ __forceinline__ int pidx(int i) { return i + (i >> 7); }

__device__ __forceinline__ float hannw(int n) {
    return 0.5f - 0.5f * __cosf((float)n * TWO_PI_OVER_WIN);
}

__device__ float norm_at(int p) {
    int f_hi = p >> 7; if (f_hi > NFRM - 1) f_hi = NFRM - 1;
    int f_lo = (p >= 384) ? ((p - 384) >> 7) : 0;
    float s = 0.f;
    for (int f = f_lo; f <= f_hi; ++f) s += hannw(p - (f << 7));
    return s;
}

__global__ void halo_zero_kernel(float* __restrict__ out) {
    int b   = blockIdx.y;
    int blk = blockIdx.x + 1;
    int u   = blk * (NFB * HOP) - PADW + (int)threadIdx.x;
    out[(size_t)b * NT + u] = 0.f;
}

// One cascade step: DST[s] = -a1[s]*SRC[s] - a2[s]*DST[s] + in(s),
// in(0)=X, in(s)=SRC[s-1]. All 11 updates independent -> 22-wide FMA ILP.
#define CASCADE(SRC, DST, X)                                          \
    DST##0  = fmaf(na2_0,  DST##0,  fmaf(na1_0,  SRC##0,  (X)));      \
    DST##1  = fmaf(na2_1,  DST##1,  fmaf(na1_1,  SRC##1,  SRC##0));   \
    DST##2  = fmaf(na2_2,  DST##2,  fmaf(na1_2,  SRC##2,  SRC##1));   \
    DST##3  = fmaf(na2_3,  DST##3,  fmaf(na1_3,  SRC##3,  SRC##2));   \
    DST##4  = fmaf(na2_4,  DST##4,  fmaf(na1_4,  SRC##4,  SRC##3));   \
    DST##5  = fmaf(na2_5,  DST##5,  fmaf(na1_5,  SRC##5,  SRC##4));   \
    DST##6  = fmaf(na2_6,  DST##6,  fmaf(na1_6,  SRC##6,  SRC##5));   \
    DST##7  = fmaf(na2_7,  DST##7,  fmaf(na1_7,  SRC##7,  SRC##6));   \
    DST##8  = fmaf(na2_8,  DST##8,  fmaf(na1_8,  SRC##8,  SRC##7));   \
    DST##9  = fmaf(na2_9,  DST##9,  fmaf(na1_9,  SRC##9,  SRC##8));   \
    DST##10 = fmaf(na2_10, DST##10, fmaf(na1_10, SRC##10, SRC##9));

#define PIX(T) (kbase + (T) + ((T) >> 7))
#define POX(T) (kbase + ((T) - 10) + (((T) - 10) >> 7))

__global__ __launch_bounds__(NFB, 1) void synth_kernel(const float* __restrict__ ex,
                                                       const float* __restrict__ gain,
                                                       const float* __restrict__ bq,
                                                       float* __restrict__ out) {
    extern __shared__ float sm[];
    float* in_s  = sm;
    float* out_s = sm + SMEMN;
    float* win_s = sm + 2 * SMEMN;

    const int b   = blockIdx.y;
    const int blk = blockIdx.x;
    const int F0  = blk * NFB;
    const int S0  = F0 * HOP;
    const int tid = (int)threadIdx.x;

    // ---- Phase A: stage input span; zero only the out_s tail (positions
    // [NFB*HOP, SPAN) have no chunk-0 first-writer); window table.
    for (int i = tid; i < SPAN; i += NFB) {
        int pos = S0 + i - PADW;
        float v = (pos >= 0 && pos < NT) ? ex[(size_t)b * NT + pos] : 0.f;
        in_s[pidx(i)] = v;
    }
    for (int i = NFB * HOP + tid; i < SPAN; i += NFB) out_s[pidx(i)] = 0.f;
    for (int i = tid; i < WINL; i += NFB)  win_s[i] = hannw(i);
    __syncthreads();

    // ---- Per-frame coefficients as named registers (negated for FMA form)
    const int f = F0 + tid;
    const float g = gain[b * NFRM + f];
    const float* bp = bq + (size_t)(b * NFRM + f) * (NSTAGE * 3);
    const float na1_0  = -bp[1],  na2_0  = -bp[2];
    const float na1_1  = -bp[4],  na2_1  = -bp[5];
    const float na1_2  = -bp[7],  na2_2  = -bp[8];
    const float na1_3  = -bp[10], na2_3  = -bp[11];
    const float na1_4  = -bp[13], na2_4  = -bp[14];
    const float na1_5  = -bp[16], na2_5  = -bp[17];
    const float na1_6  = -bp[19], na2_6  = -bp[20];
    const float na1_7  = -bp[22], na2_7  = -bp[23];
    const float na1_8  = -bp[25], na2_8  = -bp[26];
    const float na1_9  = -bp[28], na2_9  = -bp[29];
    const float na1_10 = -bp[31], na2_10 = -bp[32];

    float pa0 = 0.f, pa1 = 0.f, pa2 = 0.f, pa3 = 0.f, pa4 = 0.f, pa5 = 0.f,
          pa6 = 0.f, pa7 = 0.f, pa8 = 0.f, pa9 = 0.f, pa10 = 0.f;
    float pb0 = 0.f, pb1 = 0.f, pb2 = 0.f, pb3 = 0.f, pb4 = 0.f, pb5 = 0.f,
          pb6 = 0.f, pb7 = 0.f, pb8 = 0.f, pb9 = 0.f, pb10 = 0.f;

    const int kbase = tid * (HOP + 1);

    // ---- Phase B: pipelined cascade with software-pipelined smem prefetch.
    // Barriers at output-window boundaries (to = 128*w) keep the cross-warp
    // in-smem OLA race-free; prefetch never crosses a barrier (last pair of
    // each chunk is peeled and uses preloaded values only).

    // Prologue: t = 0..9, fill the filter pipeline, no output.
    #pragma unroll
    for (int t = 0; t < NSTAGE - 1; t += 2) {
        float x0 = in_s[PIX(t)] * g;
        float x1 = in_s[PIX(t + 1)] * g;
        CASCADE(pa, pb, x0);
        CASCADE(pb, pa, x1);
    }

    // Chunk 0: t in [10,138). First write of every OLA slot -> pure store.
    {
        float xa = in_s[PIX(10)] * g, xb = in_s[PIX(11)] * g;
        float w0 = win_s[0], w1 = win_s[1];
        #pragma unroll 4
        for (int t = 10; t < 136; t += 2) {
            float xa2 = in_s[PIX(t + 2)] * g, xb2 = in_s[PIX(t + 3)] * g;
            float w2 = win_s[t - 8], w3 = win_s[t - 7];
            CASCADE(pa, pb, xa); out_s[POX(t)]     = pb10 * w0;
            CASCADE(pb, pa, xb); out_s[POX(t + 1)] = pa10 * w1;
            xa = xa2; xb = xb2; w0 = w2; w1 = w3;
        }
        CASCADE(pa, pb, xa); out_s[POX(136)] = pb10 * w0;
        CASCADE(pb, pa, xb); out_s[POX(137)] = pa10 * w1;
        __syncthreads();
    }

    // Chunks 1,2: t in [138,266), [266,394). Accumulating OLA.
    #pragma unroll 1
    for (int c = 1; c <= 2; ++c) {
        const int t0 = 10 + 128 * c;
        float xa = in_s[PIX(t0)] * g, xb = in_s[PIX(t0 + 1)] * g;
        float oo0 = out_s[POX(t0)], oo1 = out_s[POX(t0 + 1)];
        float w0 = win_s[t0 - 10], w1 = win_s[t0 - 9];
        #pragma unroll 4
        for (int t = t0; t < t0 + 126; t += 2) {
            float xa2 = in_s[PIX(t + 2)] * g, xb2 = in_s[PIX(t + 3)] * g;
            float oo2 = out_s[POX(t + 2)], oo3 = out_s[POX(t + 3)];
            float w2 = win_s[t - 8], w3 = win_s[t - 7];
            CASCADE(pa, pb, xa); out_s[POX(t)]     = fmaf(pb10, w0, oo0);
            CASCADE(pb, pa, xb); out_s[POX(t + 1)] = fmaf(pa10, w1, oo1);
            xa = xa2; xb = xb2; oo0 = oo2; oo1 = oo3; w0 = w2; w1 = w3;
        }
        CASCADE(pa, pb, xa); out_s[POX(t0 + 126)] = fmaf(pb10, w0, oo0);
        CASCADE(pb, pa, xb); out_s[POX(t0 + 127)] = fmaf(pa10, w1, oo1);
        __syncthreads();
    }

    // Chunk 3: t in [394,522). Input exists only for t < 512 (guarded
    // prefetch); final 10 steps drain the filter pipeline with x=0.
    {
        float xa = in_s[PIX(394)] * g, xb = in_s[PIX(395)] * g;
        float oo0 = out_s[POX(394)], oo1 = out_s[POX(395)];
        float w0 = win_s[384], w1 = win_s[385];
        #pragma unroll 4
        for (int t = 394; t < 520; t += 2) {
            float xa2 = (t + 2 < 512) ? in_s[PIX(t + 2)] * g : 0.f;
            float xb2 = (t + 3 < 512) ? in_s[PIX(t + 3)] * g : 0.f;
            float oo2 = out_s[POX(t + 2)], oo3 = out_s[POX(t + 3)];
            float w2 = win_s[t - 8], w3 = win_s[t - 7];
            CASCADE(pa, pb, xa); out_s[POX(t)]     = fmaf(pb10, w0, oo0);
            CASCADE(pb, pa, xb); out_s[POX(t + 1)] = fmaf(pa10, w1, oo1);
            xa = xa2; xb = xb2; oo0 = oo2; oo1 = oo3; w0 = w2; w1 = w3;
        }
        CASCADE(pa, pb, xa); out_s[POX(520)] = fmaf(pb10, w0, oo0);
        CASCADE(pb, pa, xb); out_s[POX(521)] = fmaf(pa10, w1, oo1);
        __syncthreads();
    }

    // ---- Phase C: write out. Interior norm is exactly 2.0; halos via atomics
    // into pre-zeroed columns.
    const int lo = (F0 == 0) ? 0 : 384;
    const int hi = (F0 + NFB >= NFRM) ? SPAN : NFB * HOP;
    for (int i = tid; i < SPAN; i += NFB) {
        int p = S0 + i;
        int u = p - PADW;
        if (u < 0 || u >= NT) continue;
        float w = out_s[pidx(i)];
        if (p >= 384 && p < NFRM * HOP) w *= 0.5f;
        else                            w /= norm_at(p);
        float* dst = out + (size_t)b * NT + u;
        if (i >= lo && i < hi) *dst = w;
        else                   atomicAdd(dst, w);
    }
}

extern "C" void kernel_launch(void* const* d_in, const int* in_sizes, int n_in,
                              void* d_out, int out_size) {
    const float* ex   = (const float*)d_in[0];   // (32, 131072) f32
    const float* gain = (const float*)d_in[1];   // (32, 1024)   f32
    const float* bq   = (const float*)d_in[2];   // (32, 1024, 11, 3) f32
    float* out = (float*)d_out;                  // (32, 131072) f32

    cudaFuncSetAttribute(synth_kernel, cudaFuncAttributeMaxDynamicSharedMemorySize,
                         (int)SMEM_BYTES);

    halo_zero_kernel<<<dim3(BLK_PER_B - 1, NB), 384>>>(out);
    synth_kernel<<<dim3(BLK_PER_B, NB), NFB, SMEM_BYTES>>>(ex, gain, bq, out);
}

// round 4
// speedup vs baseline: 3.4266x; 1.5590x over previous
#include <cuda_runtime.h>
#include <cstdint>

// Problem constants
#define HOP     128
#define WINL    512
#define PADW    192
#define NB      32
#define NT      131072
#define NFRM    1024
#define NSTAGE  11

// Tiling
#define NFB     64
#define BLK_PER_B (NFRM / NFB)             // 16
#define SPAN    ((NFB - 1) * HOP + WINL)   // 8576
#define NROWS   (SPAN / HOP)               // 67
#define SMEMN   (NROWS * (HOP + 1))        // 8643 floats (129-word rows)
#define SMEM_BYTES ((SMEMN + WINL) * sizeof(float))   // 36620 B -> 6 blocks/SM

#define TWO_PI_OVER_WIN 0.012271846303085129f

__device__ __forceinline__ int pidx(int i) { return i + (i >> 7); }

__device__ __forceinline__ float hannw(int n) {
    return 0.5f - 0.5f * __cosf((float)n * TWO_PI_OVER_WIN);
}

__device__ float norm_at(int p) {
    int f_hi = p >> 7; if (f_hi > NFRM - 1) f_hi = NFRM - 1;
    int f_lo = (p >= 384) ? ((p - 384) >> 7) : 0;
    float s = 0.f;
    for (int f = f_lo; f <= f_hi; ++f) s += hannw(p - (f << 7));
    return s;
}

__global__ void halo_zero_kernel(float* __restrict__ out) {
    int b   = blockIdx.y;
    int blk = blockIdx.x + 1;
    int u   = blk * (NFB * HOP) - PADW + (int)threadIdx.x;
    out[(size_t)b * NT + u] = 0.f;
}

// One cascade step: DST[s] = -a1[s]*SRC[s] - a2[s]*DST[s] + in(s),
// in(0)=X, in(s)=SRC[s-1]. 22 independent FMAs per step.
#define CASCADE(SRC, DST, X)                                          \
    DST##0  = fmaf(na2_0,  DST##0,  fmaf(na1_0,  SRC##0,  (X)));      \
    DST##1  = fmaf(na2_1,  DST##1,  fmaf(na1_1,  SRC##1,  SRC##0));   \
    DST##2  = fmaf(na2_2,  DST##2,  fmaf(na1_2,  SRC##2,  SRC##1));   \
    DST##3  = fmaf(na2_3,  DST##3,  fmaf(na1_3,  SRC##3,  SRC##2));   \
    DST##4  = fmaf(na2_4,  DST##4,  fmaf(na1_4,  SRC##4,  SRC##3));   \
    DST##5  = fmaf(na2_5,  DST##5,  fmaf(na1_5,  SRC##5,  SRC##4));   \
    DST##6  = fmaf(na2_6,  DST##6,  fmaf(na1_6,  SRC##6,  SRC##5));   \
    DST##7  = fmaf(na2_7,  DST##7,  fmaf(na1_7,  SRC##7,  SRC##6));   \
    DST##8  = fmaf(na2_8,  DST##8,  fmaf(na1_8,  SRC##8,  SRC##7));   \
    DST##9  = fmaf(na2_9,  DST##9,  fmaf(na1_9,  SRC##9,  SRC##8));   \
    DST##10 = fmaf(na2_10, DST##10, fmaf(na1_10, SRC##10, SRC##9));

// 8-step group, accumulating OLA. ob/wb carry immediate offsets (JJ const-ish
// per unrolled iteration; (j>>7) folded into ob per chunk).
#define G8_ACC(JJ, i0, i1, i2, i3, i4, i5, i6, i7) {                  \
    float _o0 = ob[(JJ)+0], _o1 = ob[(JJ)+1],                          \
          _o2 = ob[(JJ)+2], _o3 = ob[(JJ)+3];                          \
    float _w0 = wb[(JJ)+0], _w1 = wb[(JJ)+1],                          \
          _w2 = wb[(JJ)+2], _w3 = wb[(JJ)+3];                          \
    CASCADE(pa, pb, g*(i0)); ob[(JJ)+0] = fmaf(pb10, _w0, _o0);        \
    CASCADE(pb, pa, g*(i1)); ob[(JJ)+1] = fmaf(pa10, _w1, _o1);        \
    float _o4 = ob[(JJ)+4], _o5 = ob[(JJ)+5],                          \
          _o6 = ob[(JJ)+6], _o7 = ob[(JJ)+7];                          \
    float _w4 = wb[(JJ)+4], _w5 = wb[(JJ)+5],                          \
          _w6 = wb[(JJ)+6], _w7 = wb[(JJ)+7];                          \
    CASCADE(pa, pb, g*(i2)); ob[(JJ)+2] = fmaf(pb10, _w2, _o2);        \
    CASCADE(pb, pa, g*(i3)); ob[(JJ)+3] = fmaf(pa10, _w3, _o3);        \
    CASCADE(pa, pb, g*(i4)); ob[(JJ)+4] = fmaf(pb10, _w4, _o4);        \
    CASCADE(pb, pa, g*(i5)); ob[(JJ)+5] = fmaf(pa10, _w5, _o5);        \
    CASCADE(pa, pb, g*(i6)); ob[(JJ)+6] = fmaf(pb10, _w6, _o6);        \
    CASCADE(pb, pa, g*(i7)); ob[(JJ)+7] = fmaf(pa10, _w7, _o7); }

// 8-step group, first write of each OLA slot (chunk 0): pure store.
#define G8_STORE(JJ, i0, i1, i2, i3, i4, i5, i6, i7) {                \
    float _w0 = wb[(JJ)+0], _w1 = wb[(JJ)+1],                          \
          _w2 = wb[(JJ)+2], _w3 = wb[(JJ)+3];                          \
    CASCADE(pa, pb, g*(i0)); ob[(JJ)+0] = pb10 * _w0;                  \
    CASCADE(pb, pa, g*(i1)); ob[(JJ)+1] = pa10 * _w1;                  \
    float _w4 = wb[(JJ)+4], _w5 = wb[(JJ)+5],                          \
          _w6 = wb[(JJ)+6], _w7 = wb[(JJ)+7];                          \
    CASCADE(pa, pb, g*(i2)); ob[(JJ)+2] = pb10 * _w2;                  \
    CASCADE(pb, pa, g*(i3)); ob[(JJ)+3] = pa10 * _w3;                  \
    CASCADE(pa, pb, g*(i4)); ob[(JJ)+4] = pb10 * _w4;                  \
    CASCADE(pb, pa, g*(i5)); ob[(JJ)+5] = pa10 * _w5;                  \
    CASCADE(pa, pb, g*(i6)); ob[(JJ)+6] = pb10 * _w6;                  \
    CASCADE(pb, pa, g*(i7)); ob[(JJ)+7] = pa10 * _w7; }

// Guarded 16B-aligned quad load of input elements t = 4k..4k+3.
// Offsets are multiples of 4 floats, so each quad is entirely in or out of
// [0, NT); out-of-range (the zero padding) returns zeros.
__device__ __forceinline__ float4 ld4g(const float* __restrict__ xp, int pos0, int k) {
    int pos = pos0 + 4 * k;
    if ((unsigned)pos <= (unsigned)(NT - 4))
        return *(const float4*)(xp + 4 * k);
    return make_float4(0.f, 0.f, 0.f, 0.f);
}

__global__ __launch_bounds__(NFB, 1) void synth_kernel(const float* __restrict__ ex,
                                                       const float* __restrict__ gain,
                                                       const float* __restrict__ bq,
                                                       float* __restrict__ out) {
    extern __shared__ float sm[];
    float* out_s = sm;                // SMEMN floats
    float* win_s = sm + SMEMN;        // WINL floats

    const int b   = blockIdx.y;
    const int blk = blockIdx.x;
    const int F0  = blk * NFB;
    const int S0  = F0 * HOP;
    const int tid = (int)threadIdx.x;
    const int kbase = tid * (HOP + 1);

    // Per-thread input stream base (element for t=0; may be out of range at edges)
    const int   pos0 = S0 + tid * HOP - PADW;
    const float* xp  = ex + (size_t)b * NT + pos0;

    // Issue first input quads early (t = 0..19)
    float4 q0 = ld4g(xp, pos0, 0);
    float4 q1 = ld4g(xp, pos0, 1);
    float4 q2 = ld4g(xp, pos0, 2);
    float4 qa = ld4g(xp, pos0, 3);
    float4 qb = ld4g(xp, pos0, 4);

    // ---- Phase A: zero out_s tail rows (no chunk-0 first-writer), window table
    for (int i = NFB * HOP + tid; i < SPAN; i += NFB) out_s[pidx(i)] = 0.f;
    for (int i = tid; i < WINL; i += NFB) win_s[i] = hannw(i);

    // ---- Per-frame coefficients (negated for FMA form)
    const int f = F0 + tid;
    const float g = gain[b * NFRM + f];
    const float* bp = bq + (size_t)(b * NFRM + f) * (NSTAGE * 3);
    const float na1_0  = -bp[1],  na2_0  = -bp[2];
    const float na1_1  = -bp[4],  na2_1  = -bp[5];
    const float na1_2  = -bp[7],  na2_2  = -bp[8];
    const float na1_3  = -bp[10], na2_3  = -bp[11];
    const float na1_4  = -bp[13], na2_4  = -bp[14];
    const float na1_5  = -bp[16], na2_5  = -bp[17];
    const float na1_6  = -bp[19], na2_6  = -bp[20];
    const float na1_7  = -bp[22], na2_7  = -bp[23];
    const float na1_8  = -bp[25], na2_8  = -bp[26];
    const float na1_9  = -bp[28], na2_9  = -bp[29];
    const float na1_10 = -bp[31], na2_10 = -bp[32];

    float pa0 = 0.f, pa1 = 0.f, pa2 = 0.f, pa3 = 0.f, pa4 = 0.f, pa5 = 0.f,
          pa6 = 0.f, pa7 = 0.f, pa8 = 0.f, pa9 = 0.f, pa10 = 0.f;
    float pb0 = 0.f, pb1 = 0.f, pb2 = 0.f, pb3 = 0.f, pb4 = 0.f, pb5 = 0.f,
          pb6 = 0.f, pb7 = 0.f, pb8 = 0.f, pb9 = 0.f, pb10 = 0.f;

    __syncthreads();   // out_s tail + win_s ready

    // ---- Prologue: t = 0..9 fill the filter pipeline (no output)
    CASCADE(pa, pb, g * q0.x); CASCADE(pb, pa, g * q0.y);
    CASCADE(pa, pb, g * q0.z); CASCADE(pb, pa, g * q0.w);
    CASCADE(pa, pb, g * q1.x); CASCADE(pb, pa, g * q1.y);
    CASCADE(pa, pb, g * q1.z); CASCADE(pb, pa, g * q1.w);
    CASCADE(pa, pb, g * q2.x); CASCADE(pb, pa, g * q2.y);
    float x0 = q2.z, x1 = q2.w;           // t = 10, 11

    // ---- Chunk 0: t in [10,138), outputs j in [0,128). Pure stores.
    {
        float* ob = out_s + kbase;
        const float* wb = win_s;
        #pragma unroll 2
        for (int m = 0; m < 16; ++m) {
            float4 qa_n = ld4g(xp, pos0, 5 + 2 * m);
            float4 qb_n = ld4g(xp, pos0, 6 + 2 * m);
            G8_STORE(m * 8, x0, x1, qa.x, qa.y, qa.z, qa.w, qb.x, qb.y);
            x0 = qb.z; x1 = qb.w; qa = qa_n; qb = qb_n;
        }
        __syncthreads();
    }

    // ---- Chunks 1,2: accumulating OLA.
    #pragma unroll 1
    for (int c = 1; c <= 2; ++c) {
        float* ob = out_s + kbase + 128 * c + c;   // (j>>7)==c folded in
        const float* wb = win_s + 128 * c;
        const int kq0 = 5 + 32 * c;
        #pragma unroll 2
        for (int m = 0; m < 16; ++m) {
            float4 qa_n = ld4g(xp, pos0, kq0 + 2 * m);
            float4 qb_n = ld4g(xp, pos0, kq0 + 1 + 2 * m);
            G8_ACC(m * 8, x0, x1, qa.x, qa.y, qa.z, qa.w, qb.x, qb.y);
            x0 = qb.z; x1 = qb.w; qa = qa_n; qb = qb_n;
        }
        __syncthreads();
    }

    // ---- Chunk 3: t in [394,522). Inputs exist only for t < 512; the final
    // two groups are peeled with zero inputs (drain).
    {
        float* ob = out_s + kbase + 384 + 3;
        const float* wb = win_s + 384;
        #pragma unroll 2
        for (int m = 0; m < 14; ++m) {
            float4 qa_n = ld4g(xp, pos0, 101 + 2 * m);
            float4 qb_n = ld4g(xp, pos0, 102 + 2 * m);
            G8_ACC(m * 8, x0, x1, qa.x, qa.y, qa.z, qa.w, qb.x, qb.y);
            x0 = qb.z; x1 = qb.w; qa = qa_n; qb = qb_n;
        }
        // group 14: t = 506..513 (qa = t508..511 valid; t512,513 forced 0)
        G8_ACC(112, x0, x1, qa.x, qa.y, qa.z, qa.w, 0.f, 0.f);
        // group 15: t = 514..521, all-zero input drain
        G8_ACC(120, 0.f, 0.f, 0.f, 0.f, 0.f, 0.f, 0.f, 0.f);
        __syncthreads();
    }

    // ---- Phase C: write out. Interior norm == 2.0; halos via atomics into
    // pre-zeroed columns.
    const int lo = (F0 == 0) ? 0 : 384;
    const int hi = (F0 + NFB >= NFRM) ? SPAN : NFB * HOP;
    for (int i = tid; i < SPAN; i += NFB) {
        int p = S0 + i;
        int u = p - PADW;
        if (u < 0 || u >= NT) continue;
        float w = out_s[pidx(i)];
        if (p >= 384 && p < NFRM * HOP) w *= 0.5f;
        else                            w /= norm_at(p);
        float* dst = out + (size_t)b * NT + u;
        if (i >= lo && i < hi) *dst = w;
        else                   atomicAdd(dst, w);
    }
}

extern "C" void kernel_launch(void* const* d_in, const int* in_sizes, int n_in,
                              void* d_out, int out_size) {
    const float* ex   = (const float*)d_in[0];   // (32, 131072) f32
    const float* gain = (const float*)d_in[1];   // (32, 1024)   f32
    const float* bq   = (const float*)d_in[2];   // (32, 1024, 11, 3) f32
    float* out = (float*)d_out;                  // (32, 131072) f32

    cudaFuncSetAttribute(synth_kernel, cudaFuncAttributeMaxDynamicSharedMemorySize,
                         (int)SMEM_BYTES);

    halo_zero_kernel<<<dim3(BLK_PER_B - 1, NB), 384>>>(out);
    synth_kernel<<<dim3(BLK_PER_B, NB), NFB, SMEM_BYTES>>>(ex, gain, bq, out);
}

// round 5
// speedup vs baseline: 3.5600x; 1.0389x over previous
#include <cuda_runtime.h>
#include <cstdint>

// Problem constants
#define HOP     128
#define WINL    512
#define PADW    192
#define NB      32
#define NT      131072
#define NFRM    1024
#define NSTAGE  11

// Tiling: one warp per block, one frame per lane
#define NFB     32
#define BLK_PER_B (NFRM / NFB)             // 32
#define SPAN    ((NFB - 1) * HOP + WINL)   // 4480
#define NROWS   (SPAN / HOP)               // 35
#define SMEMN   (NROWS * (HOP + 1))        // 4515 floats (129-word rows)
#define SMEM_BYTES ((SMEMN + WINL) * sizeof(float))   // ~20.1 KB

#define TWO_PI_OVER_WIN 0.012271846303085129f

__device__ __forceinline__ int pidx(int i) { return i + (i >> 7); }

__device__ __forceinline__ float hannw(int n) {
    return 0.5f - 0.5f * __cosf((float)n * TWO_PI_OVER_WIN);
}

__device__ float norm_at(int p) {
    int f_hi = p >> 7; if (f_hi > NFRM - 1) f_hi = NFRM - 1;
    int f_lo = (p >= 384) ? ((p - 384) >> 7) : 0;
    float s = 0.f;
    for (int f = f_lo; f <= f_hi; ++f) s += hannw(p - (f << 7));
    return s;
}

__global__ void halo_zero_kernel(float* __restrict__ out) {
    int b   = blockIdx.y;
    int blk = blockIdx.x + 1;
    int u   = blk * (NFB * HOP) - PADW + (int)threadIdx.x;
    out[(size_t)b * NT + u] = 0.f;
}

// One cascade step: DST[s] = -a1[s]*SRC[s] - a2[s]*DST[s] + in(s),
// in(0)=X, in(s)=SRC[s-1]. 22 independent FMAs per step.
#define CASCADE(SRC, DST, X)                                          \
    DST##0  = fmaf(na2_0,  DST##0,  fmaf(na1_0,  SRC##0,  (X)));      \
    DST##1  = fmaf(na2_1,  DST##1,  fmaf(na1_1,  SRC##1,  SRC##0));   \
    DST##2  = fmaf(na2_2,  DST##2,  fmaf(na1_2,  SRC##2,  SRC##1));   \
    DST##3  = fmaf(na2_3,  DST##3,  fmaf(na1_3,  SRC##3,  SRC##2));   \
    DST##4  = fmaf(na2_4,  DST##4,  fmaf(na1_4,  SRC##4,  SRC##3));   \
    DST##5  = fmaf(na2_5,  DST##5,  fmaf(na1_5,  SRC##5,  SRC##4));   \
    DST##6  = fmaf(na2_6,  DST##6,  fmaf(na1_6,  SRC##6,  SRC##5));   \
    DST##7  = fmaf(na2_7,  DST##7,  fmaf(na1_7,  SRC##7,  SRC##6));   \
    DST##8  = fmaf(na2_8,  DST##8,  fmaf(na1_8,  SRC##8,  SRC##7));   \
    DST##9  = fmaf(na2_9,  DST##9,  fmaf(na1_9,  SRC##9,  SRC##8));   \
    DST##10 = fmaf(na2_10, DST##10, fmaf(na1_10, SRC##10, SRC##9));

// 8-step group, accumulating OLA. ob/wb carry immediate offsets.
#define G8_ACC(JJ, i0, i1, i2, i3, i4, i5, i6, i7) {                  \
    float _o0 = ob[(JJ)+0], _o1 = ob[(JJ)+1],                          \
          _o2 = ob[(JJ)+2], _o3 = ob[(JJ)+3];                          \
    float _w0 = wb[(JJ)+0], _w1 = wb[(JJ)+1],                          \
          _w2 = wb[(JJ)+2], _w3 = wb[(JJ)+3];                          \
    CASCADE(pa, pb, g*(i0)); ob[(JJ)+0] = fmaf(pb10, _w0, _o0);        \
    CASCADE(pb, pa, g*(i1)); ob[(JJ)+1] = fmaf(pa10, _w1, _o1);        \
    float _o4 = ob[(JJ)+4], _o5 = ob[(JJ)+5],                          \
          _o6 = ob[(JJ)+6], _o7 = ob[(JJ)+7];                          \
    float _w4 = wb[(JJ)+4], _w5 = wb[(JJ)+5],                          \
          _w6 = wb[(JJ)+6], _w7 = wb[(JJ)+7];                          \
    CASCADE(pa, pb, g*(i2)); ob[(JJ)+2] = fmaf(pb10, _w2, _o2);        \
    CASCADE(pb, pa, g*(i3)); ob[(JJ)+3] = fmaf(pa10, _w3, _o3);        \
    CASCADE(pa, pb, g*(i4)); ob[(JJ)+4] = fmaf(pb10, _w4, _o4);        \
    CASCADE(pb, pa, g*(i5)); ob[(JJ)+5] = fmaf(pa10, _w5, _o5);        \
    CASCADE(pa, pb, g*(i6)); ob[(JJ)+6] = fmaf(pb10, _w6, _o6);        \
    CASCADE(pb, pa, g*(i7)); ob[(JJ)+7] = fmaf(pa10, _w7, _o7); }

// 8-step group, first write of each OLA slot (chunk 0): pure store.
#define G8_STORE(JJ, i0, i1, i2, i3, i4, i5, i6, i7) {                \
    float _w0 = wb[(JJ)+0], _w1 = wb[(JJ)+1],                          \
          _w2 = wb[(JJ)+2], _w3 = wb[(JJ)+3];                          \
    CASCADE(pa, pb, g*(i0)); ob[(JJ)+0] = pb10 * _w0;                  \
    CASCADE(pb, pa, g*(i1)); ob[(JJ)+1] = pa10 * _w1;                  \
    float _w4 = wb[(JJ)+4], _w5 = wb[(JJ)+5],                          \
          _w6 = wb[(JJ)+6], _w7 = wb[(JJ)+7];                          \
    CASCADE(pa, pb, g*(i2)); ob[(JJ)+2] = pb10 * _w2;                  \
    CASCADE(pb, pa, g*(i3)); ob[(JJ)+3] = pa10 * _w3;                  \
    CASCADE(pa, pb, g*(i4)); ob[(JJ)+4] = pb10 * _w4;                  \
    CASCADE(pb, pa, g*(i5)); ob[(JJ)+5] = pa10 * _w5;                  \
    CASCADE(pa, pb, g*(i6)); ob[(JJ)+6] = pb10 * _w6;                  \
    CASCADE(pb, pa, g*(i7)); ob[(JJ)+7] = pa10 * _w7; }

// 16-step superstep (carry x0,x1 + quads c0..c3; updates carry).
#define SS16_ACC(JJ)                                                   \
    G8_ACC((JJ),     x0,   x1,   c0.x, c0.y, c0.z, c0.w, c1.x, c1.y)   \
    G8_ACC((JJ) + 8, c1.z, c1.w, c2.x, c2.y, c2.z, c2.w, c3.x, c3.y)

#define SS16_STORE(JJ)                                                 \
    G8_STORE((JJ),     x0,   x1,   c0.x, c0.y, c0.z, c0.w, c1.x, c1.y) \
    G8_STORE((JJ) + 8, c1.z, c1.w, c2.x, c2.y, c2.z, c2.w, c3.x, c3.y)

// Guarded 16B-aligned quad load of input elements t = 4k..4k+3.
__device__ __forceinline__ float4 ld4g(const float* __restrict__ xp, int pos0, int k) {
    int pos = pos0 + 4 * k;
    if ((unsigned)pos <= (unsigned)(NT - 4))
        return *(const float4*)(xp + 4 * k);
    return make_float4(0.f, 0.f, 0.f, 0.f);
}

__global__ __launch_bounds__(NFB) void synth_kernel(const float* __restrict__ ex,
                                                    const float* __restrict__ gain,
                                                    const float* __restrict__ bq,
                                                    float* __restrict__ out) {
    extern __shared__ float sm[];
    float* out_s = sm;                // SMEMN floats
    float* win_s = sm + SMEMN;        // WINL floats

    const int b   = blockIdx.y;
    const int blk = blockIdx.x;
    const int F0  = blk * NFB;
    const int S0  = F0 * HOP;
    const int tid = (int)threadIdx.x;
    const int kbase = tid * (HOP + 1);

    // Per-thread input stream (element t=0; may be out of range at edges)
    const int   pos0 = S0 + tid * HOP - PADW;
    const float* xp  = ex + (size_t)b * NT + pos0;

    // Early loads: prologue quads q0..q2, superstep-0 quads c0..c3 (q3..q6)
    float4 q0 = ld4g(xp, pos0, 0);
    float4 q1 = ld4g(xp, pos0, 1);
    float4 q2 = ld4g(xp, pos0, 2);
    float4 c0 = ld4g(xp, pos0, 3);
    float4 c1 = ld4g(xp, pos0, 4);
    float4 c2 = ld4g(xp, pos0, 5);
    float4 c3 = ld4g(xp, pos0, 6);

    // ---- Phase A: zero out_s tail rows; window table
    for (int i = NFB * HOP + tid; i < SPAN; i += NFB) out_s[pidx(i)] = 0.f;
    for (int i = tid; i < WINL; i += NFB) win_s[i] = hannw(i);

    // ---- Per-frame coefficients (negated for FMA form)
    const int f = F0 + tid;
    const float g = gain[b * NFRM + f];
    const float* bp = bq + (size_t)(b * NFRM + f) * (NSTAGE * 3);
    const float na1_0  = -bp[1],  na2_0  = -bp[2];
    const float na1_1  = -bp[4],  na2_1  = -bp[5];
    const float na1_2  = -bp[7],  na2_2  = -bp[8];
    const float na1_3  = -bp[10], na2_3  = -bp[11];
    const float na1_4  = -bp[13], na2_4  = -bp[14];
    const float na1_5  = -bp[16], na2_5  = -bp[17];
    const float na1_6  = -bp[19], na2_6  = -bp[20];
    const float na1_7  = -bp[22], na2_7  = -bp[23];
    const float na1_8  = -bp[25], na2_8  = -bp[26];
    const float na1_9  = -bp[28], na2_9  = -bp[29];
    const float na1_10 = -bp[31], na2_10 = -bp[32];

    float pa0 = 0.f, pa1 = 0.f, pa2 = 0.f, pa3 = 0.f, pa4 = 0.f, pa5 = 0.f,
          pa6 = 0.f, pa7 = 0.f, pa8 = 0.f, pa9 = 0.f, pa10 = 0.f;
    float pb0 = 0.f, pb1 = 0.f, pb2 = 0.f, pb3 = 0.f, pb4 = 0.f, pb5 = 0.f,
          pb6 = 0.f, pb7 = 0.f, pb8 = 0.f, pb9 = 0.f, pb10 = 0.f;

    __syncwarp();   // out_s tail + win_s visible warp-wide

    // ---- Prologue: t = 0..9 fill the filter pipeline (no output)
    CASCADE(pa, pb, g * q0.x); CASCADE(pb, pa, g * q0.y);
    CASCADE(pa, pb, g * q0.z); CASCADE(pb, pa, g * q0.w);
    CASCADE(pa, pb, g * q1.x); CASCADE(pb, pa, g * q1.y);
    CASCADE(pa, pb, g * q1.z); CASCADE(pb, pa, g * q1.w);
    CASCADE(pa, pb, g * q2.x); CASCADE(pb, pa, g * q2.y);
    float x0 = q2.z, x1 = q2.w;           // carry: t = 10, 11

    // ---- Chunk 0: t in [10,138). Pure stores. Prefetch next superstep's
    // 4 quads (16 steps ahead) each superstep; rotation renamed via unroll.
    {
        float* ob = out_s + kbase;
        const float* wb = win_s;
        #pragma unroll 2
        for (int ss = 0; ss < 8; ++ss) {
            const int kq = 7 + 4 * ss;              // quads for superstep ss+1
            float4 n0 = ld4g(xp, pos0, kq);
            float4 n1 = ld4g(xp, pos0, kq + 1);
            float4 n2 = ld4g(xp, pos0, kq + 2);
            float4 n3 = ld4g(xp, pos0, kq + 3);
            SS16_STORE(ss * 16);
            x0 = c3.z; x1 = c3.w;
            c0 = n0; c1 = n1; c2 = n2; c3 = n3;
        }
        __syncwarp();
    }

    // ---- Chunks 1,2: accumulating OLA.
    #pragma unroll 1
    for (int c = 1; c <= 2; ++c) {
        float* ob = out_s + kbase + 128 * c + c;    // (j>>7)==c folded in
        const float* wb = win_s + 128 * c;
        const int kqb = 7 + 32 * c;
        #pragma unroll 2
        for (int ss = 0; ss < 8; ++ss) {
            const int kq = kqb + 4 * ss;
            float4 n0 = ld4g(xp, pos0, kq);
            float4 n1 = ld4g(xp, pos0, kq + 1);
            float4 n2 = ld4g(xp, pos0, kq + 2);
            float4 n3 = ld4g(xp, pos0, kq + 3);
            SS16_ACC(ss * 16);
            x0 = c3.z; x1 = c3.w;
            c0 = n0; c1 = n1; c2 = n2; c3 = n3;
        }
        __syncwarp();
    }

    // ---- Chunk 3: t in [394,522). Supersteps 0..5 uniform (prefetching up to
    // quad 126); superstep 6 peeled (prefetch only q127); superstep 7 peeled
    // with zero-input drain for t >= 512.
    {
        float* ob = out_s + kbase + 384 + 3;
        const float* wb = win_s + 384;
        #pragma unroll 2
        for (int ss = 0; ss < 6; ++ss) {
            const int kq = 103 + 4 * ss;
            float4 n0 = ld4g(xp, pos0, kq);
            float4 n1 = ld4g(xp, pos0, kq + 1);
            float4 n2 = ld4g(xp, pos0, kq + 2);
            float4 n3 = ld4g(xp, pos0, kq + 3);
            SS16_ACC(ss * 16);
            x0 = c3.z; x1 = c3.w;
            c0 = n0; c1 = n1; c2 = n2; c3 = n3;
        }
        // superstep 6: t = 490..505 (quads 123..126 in c0..c3); fetch q127
        float4 qq = ld4g(xp, pos0, 127);
        SS16_ACC(96);
        x0 = c3.z; x1 = c3.w;                        // t = 506, 507
        // superstep 7: t = 506..521; inputs valid through t=511 (qq), then 0
        G8_ACC(112, x0, x1, qq.x, qq.y, qq.z, qq.w, 0.f, 0.f);
        G8_ACC(120, 0.f, 0.f, 0.f, 0.f, 0.f, 0.f, 0.f, 0.f);
        __syncwarp();
    }

    // ---- Phase C: write out. Interior norm == 2.0; halos via atomics into
    // pre-zeroed columns.
    const int lo = (F0 == 0) ? 0 : 384;
    const int hi = (F0 + NFB >= NFRM) ? SPAN : NFB * HOP;
    for (int i = tid; i < SPAN; i += NFB) {
        int p = S0 + i;
        int u = p - PADW;
        if (u < 0 || u >= NT) continue;
        float w = out_s[pidx(i)];
        if (p >= 384 && p < NFRM * HOP) w *= 0.5f;
        else                            w /= norm_at(p);
        float* dst = out + (size_t)b * NT + u;
        if (i >= lo && i < hi) *dst = w;
        else                   atomicAdd(dst, w);
    }
}

extern "C" void kernel_launch(void* const* d_in, const int* in_sizes, int n_in,
                              void* d_out, int out_size) {
    const float* ex   = (const float*)d_in[0];   // (32, 131072) f32
    const float* gain = (const float*)d_in[1];   // (32, 1024)   f32
    const float* bq   = (const float*)d_in[2];   // (32, 1024, 11, 3) f32
    float* out = (float*)d_out;                  // (32, 131072) f32

    cudaFuncSetAttribute(synth_kernel, cudaFuncAttributeMaxDynamicSharedMemorySize,
                         (int)SMEM_BYTES);

    halo_zero_kernel<<<dim3(BLK_PER_B - 1, NB), 384>>>(out);
    synth_kernel<<<dim3(BLK_PER_B, NB), NFB, SMEM_BYTES>>>(ex, gain, bq, out);
}